// round 4
// baseline (speedup 1.0000x reference)
#include <cuda_runtime.h>
#include <stdint.h>

// Sort_Latent_Layer: z (B, 1, 8192) fp32. Per row: 512 packets of 16 floats,
// stable-sort packets by packet[0] ascending, gather, write back.
//
// One CTA per row, 512 threads (1 thread per packet).
//  - Stage row in smem as float4, padded 1 float4 per packet (5 float4 slots)
//    -> conflict-free linear stores, good gather reads.
//  - Keys extracted during staging (w==0 lane of each packet).
//  - Key packed to sortable u64: monotone uint32 of float in high bits,
//    original index in low bits -> unique items, tie-break = stable sort.
//  - Bitonic sort: distances j>=32 via smem, j<32 via __shfl_xor_sync.
//  - Gather from smem, coalesced float4 writes.

#define NPK   512   // packets per row
#define DPAD  5     // float4 slots per packet (4 data + 1 pad)

__global__ void __launch_bounds__(512, 1)
sort_latent_kernel(const float* __restrict__ z, float* __restrict__ out)
{
    __shared__ float4             sdata[NPK * DPAD];   // 40 KB
    __shared__ unsigned long long ssort[NPK];          //  4 KB
    __shared__ uint32_t           skeys[NPK];          //  2 KB (keys, then inds)

    const int tid = threadIdx.x;
    const long long row = blockIdx.x;
    const float4* __restrict__ in4 = (const float4*)(z + row * 8192);

    // ---- stage row into smem, harvest keys ----
    #pragma unroll
    for (int it = 0; it < 4; ++it) {
        int f = tid + it * 512;          // float4 index within row, 0..2047
        float4 v = in4[f];
        int p = f >> 2, w = f & 3;
        sdata[p * DPAD + w] = v;
        if (w == 0) skeys[p] = __float_as_uint(v.x);
    }
    __syncthreads();

    // ---- build sortable item ----
    uint32_t kb = skeys[tid];
    kb = (kb & 0x80000000u) ? ~kb : (kb | 0x80000000u);   // monotone float->uint
    unsigned long long item =
        ((unsigned long long)kb << 32) | (unsigned long long)(uint32_t)tid;

    // ---- bitonic sort, 512 items, ascending ----
    #pragma unroll 1
    for (int k = 2; k <= 512; k <<= 1) {
        const bool dir_up = ((tid & k) == 0);

        // cross-warp stages via smem
        #pragma unroll 1
        for (int j = k >> 1; j >= 32; j >>= 1) {
            __syncthreads();             // protect prior reads of ssort
            ssort[tid] = item;
            __syncthreads();
            unsigned long long other = ssort[tid ^ j];
            bool keep_min = (((tid & j) == 0) == dir_up);
            if ((other < item) == keep_min) item = other;
        }

        // intra-warp stages via shfl
        int jstart = (k >> 1) < 16 ? (k >> 1) : 16;
        #pragma unroll 1
        for (int j = jstart; j >= 1; j >>= 1) {
            unsigned long long other = __shfl_xor_sync(0xFFFFFFFFu, item, j);
            bool keep_min = (((tid & j) == 0) == dir_up);
            if ((other < item) == keep_min) item = other;
        }
    }

    // ---- publish permutation ----
    __syncthreads();
    skeys[tid] = (uint32_t)(item & 0xFFFFFFFFu);   // inds[tid] = source packet
    __syncthreads();

    // ---- gather from smem, coalesced write ----
    float4* __restrict__ out4 = (float4*)(out + row * 8192);
    #pragma unroll
    for (int it = 0; it < 4; ++it) {
        int f = tid + it * 512;
        int p = f >> 2, w = f & 3;
        int src = (int)skeys[p];
        out4[f] = sdata[src * DPAD + w];
    }
}

extern "C" void kernel_launch(void* const* d_in, const int* in_sizes, int n_in,
                              void* d_out, int out_size)
{
    const float* z  = (const float*)d_in[0];
    float* out      = (float*)d_out;
    const int D = 8192;                 // n_packets(512) * packet(16)
    int B = in_sizes[0] / D;            // 4096
    sort_latent_kernel<<<B, 512>>>(z, out);
}

// round 5
// speedup vs baseline: 1.0059x; 1.0059x over previous
#include <cuda_runtime.h>
#include <stdint.h>

// Sort_Latent_Layer: z (B, 1, 8192) fp32. Per row: 512 packets x 16 floats,
// stable-sort packets by packet[0] ascending, gather, write back.
//
// R4 design: one WARP per row, 16 items per lane held in registers.
//  - Bitonic network on i = lane*16 + v:
//      j < 16  -> register-local compare-exchange (30 of 45 stages, no comm)
//      j >= 16 -> __shfl_xor (15 stages), NO smem, NO __syncthreads
//  - Item = (monotone-uint32 key << 32) | index  -> unique, stable tiebreak.
//  - Permutation published to a tiny smem array (u16), then gather goes
//    global->global: 4 consecutive lanes read one 64B-contiguous packet
//    (full sector utilization), writes perfectly coalesced.

#define NPK 512
#define V   16
#define ROWS_PER_CTA 4
#define THREADS (32 * ROWS_PER_CTA)

__device__ __forceinline__ void ce(unsigned long long &x, unsigned long long &y, bool up)
{
    // ensure x<y ordering ascending iff up; items are distinct
    bool sw = (x > y) == up;
    unsigned long long a = sw ? y : x;
    unsigned long long b = sw ? x : y;
    x = a; y = b;
}

__global__ void __launch_bounds__(THREADS, 7)
sort_latent_kernel(const float* __restrict__ z, float* __restrict__ out, int B)
{
    __shared__ uint16_t sperm[ROWS_PER_CTA][NPK];

    const int lane = threadIdx.x & 31;
    const int w    = threadIdx.x >> 5;
    const int row  = blockIdx.x * ROWS_PER_CTA + w;
    if (row >= B) return;                       // whole-warp exit, no CTA barriers used

    const float* __restrict__ zr = z + (long long)row * 8192;

    // ---- load keys (strided, 32B sectors land in L2 for the later gather) ----
    unsigned long long it[V];
    #pragma unroll
    for (int v = 0; v < V; ++v) {
        int i = lane * V + v;                   // blocked item assignment
        uint32_t kb = __float_as_uint(zr[i * 16]);
        kb = (kb & 0x80000000u) ? ~kb : (kb | 0x80000000u);  // monotone float->uint
        it[v] = ((unsigned long long)kb << 32) | (unsigned)i;
    }

    // ---- bitonic phase A: k = 2..16, all register-local (j < 16) ----
    #pragma unroll
    for (int k = 2; k <= V; k <<= 1) {
        #pragma unroll
        for (int j = k >> 1; j >= 1; j >>= 1) {
            #pragma unroll
            for (int v = 0; v < V; ++v) {
                if ((v & j) == 0) {
                    int i = lane * V + v;
                    bool up = ((i & k) == 0);   // compile-time for k<=8, lane-bit for k=16
                    ce(it[v], it[v | j], up);
                }
            }
        }
    }

    // ---- bitonic phase B: k = 32..512 ----
    #pragma unroll
    for (int k = 32; k <= 512; k <<= 1) {
        const bool up = ((lane & (k >> 4)) == 0);       // k=512 -> always up
        // cross-lane stages: j = k/2 .. 16  (shfl only)
        #pragma unroll
        for (int j = k >> 1; j >= V; j >>= 1) {
            const int  dl      = j >> 4;                 // lane xor distance
            const bool keepmin = (((lane & dl) == 0) == up);
            #pragma unroll
            for (int v = 0; v < V; ++v) {
                unsigned long long other = __shfl_xor_sync(0xFFFFFFFFu, it[v], dl);
                if ((other < it[v]) == keepmin) it[v] = other;
            }
        }
        // register-local tail: j = 8..1, direction uniform per lane
        #pragma unroll
        for (int j = V >> 1; j >= 1; j >>= 1) {
            #pragma unroll
            for (int v = 0; v < V; ++v)
                if ((v & j) == 0) ce(it[v], it[v | j], up);
        }
    }

    // ---- publish permutation (dest packet d = lane*16+v, src = idx bits) ----
    uint16_t* p = sperm[w];
    #pragma unroll
    for (int v = 0; v < V; ++v)
        p[lane * V + v] = (uint16_t)(it[v] & 0x1FFu);
    __syncwarp();

    // ---- gather: global -> global ----
    // f enumerates row float4s with lanes consecutive -> coalesced writes;
    // 4 consecutive lanes read one contiguous 64B packet chunk -> full sectors.
    const float4* __restrict__ in4  = (const float4*)zr;
    float4* __restrict__       out4 = (float4*)(out + (long long)row * 8192);
    #pragma unroll 8
    for (int jj = 0; jj < 64; ++jj) {
        int f   = jj * 32 + lane;
        int src = p[f >> 2];
        out4[f] = in4[src * 4 + (f & 3)];
    }
}

extern "C" void kernel_launch(void* const* d_in, const int* in_sizes, int n_in,
                              void* d_out, int out_size)
{
    const float* z = (const float*)d_in[0];
    float* out     = (float*)d_out;
    const int D = 8192;                  // 512 packets * 16 floats
    int B = in_sizes[0] / D;             // 4096
    int grid = (B + ROWS_PER_CTA - 1) / ROWS_PER_CTA;
    sort_latent_kernel<<<grid, THREADS>>>(z, out, B);
}